// round 9
// baseline (speedup 1.0000x reference)
#include <cuda_runtime.h>
#include <cstdint>

#define COLS      32768
#define ROWS_MAX  8192
#define K_TOP     64
#define NT1       512            // kernel 1 block
#define NT2       256            // kernel 2 block
#define CAP       1536           // expected ~745 candidates, sigma~27 -> ~29 sigma headroom
#define EQCAP     256
#define PIVOT     2.0f           // well below the expected 64th-largest (~2.88σ); slow path covers the rest

// --- device scratch (sanctioned: no allocation allowed) ---
__device__ unsigned long long g_cand[(size_t)ROWS_MAX * CAP];   // (bits<<32)|idx
__device__ int                g_ncand[ROWS_MAX];

__device__ __forceinline__ unsigned sortable_bits(float f) {
    unsigned u = __float_as_uint(f);
    return (u & 0x80000000u) ? ~u : (u | 0x80000000u);
}
__device__ __forceinline__ float unsortable_bits(unsigned s) {
    unsigned u = (s & 0x80000000u) ? (s & 0x7fffffffu) : ~s;
    return __uint_as_float(u);
}

// =====================================================================================
// Kernel 1: pure streaming — read row, write zeros, compact rare candidates to scratch.
// =====================================================================================
__global__ __launch_bounds__(NT1)
void stream_compact_kernel(const float* __restrict__ x, float* __restrict__ out) {
    __shared__ unsigned       cb[CAP];
    __shared__ unsigned short ci[CAP];
    __shared__ int            nc;

    const int row = blockIdx.x;
    const int tid = threadIdx.x;

    const float4* __restrict__ xr   = reinterpret_cast<const float4*>(x + (size_t)row * COLS);
    float4* __restrict__       outr = reinterpret_cast<float4*>(out + (size_t)row * COLS);

    if (tid == 0) nc = 0;
    __syncthreads();

    const float4 z = make_float4(0.f, 0.f, 0.f, 0.f);
    constexpr int ITER = COLS / 4 / NT1;   // 16
    #pragma unroll
    for (int i = 0; i < ITER; i += 4) {
        float4 v[4];
        #pragma unroll
        for (int u = 0; u < 4; ++u) v[u] = __ldcs(&xr[tid + (i + u) * NT1]);
        #pragma unroll
        for (int u = 0; u < 4; ++u) __stcs(&outr[tid + (i + u) * NT1], z);
        #pragma unroll
        for (int u = 0; u < 4; ++u) {
            const float4 w = v[u];
            if (fmaxf(fmaxf(w.x, w.y), fmaxf(w.z, w.w)) >= PIVOT) {   // rare (~8.7%)
                const int j4 = (tid + (i + u) * NT1) * 4;
                #pragma unroll
                for (int c = 0; c < 4; ++c) {
                    const float val = (c == 0) ? w.x : (c == 1) ? w.y : (c == 2) ? w.z : w.w;
                    if (val >= PIVOT) {
                        int pos = atomicAdd(&nc, 1);
                        if (pos < CAP) {
                            cb[pos] = __float_as_uint(val);   // positive -> bit order = value order
                            ci[pos] = (unsigned short)(j4 + c);
                        }
                    }
                }
            }
        }
    }
    __syncthreads();

    const int n = nc;
    if (tid == 0) g_ncand[row] = n;
    const int m = (n < CAP) ? n : CAP;
    unsigned long long* __restrict__ gc = &g_cand[(size_t)row * CAP];
    for (int j = tid; j < m; j += NT1)
        gc[j] = ((unsigned long long)cb[j] << 32) | (unsigned long long)ci[j];
}

// =====================================================================================
// Kernel 2: per-row exact K-th-largest radix select + tie-break + scatter (tiny).
// =====================================================================================
__global__ __launch_bounds__(NT2)
void select_scatter_kernel(const float* __restrict__ x, float* __restrict__ out) {
    __shared__ unsigned       cb[CAP];
    __shared__ unsigned short ci[CAP];
    __shared__ unsigned short eq_idx[EQCAP];
    __shared__ int            hist[256];
    __shared__ unsigned       cur_s;
    __shared__ int            k_s;
    __shared__ int            cnt_s;
    __shared__ int            eq_cnt;

    const int row  = blockIdx.x;
    const int tid  = threadIdx.x;
    const int lane = tid & 31;

    const float* __restrict__ xrow = x + (size_t)row * COLS;
    float* __restrict__       orow = out + (size_t)row * COLS;

    if (tid == 0) eq_cnt = 0;
    __syncthreads();

    const int ncand = g_ncand[row];

    if (ncand >= K_TOP && ncand <= CAP) {
        // load candidate list (mostly L2-resident) into smem
        const unsigned long long* __restrict__ gc = &g_cand[(size_t)row * CAP];
        for (int j = tid; j < ncand; j += NT2) {
            unsigned long long p = gc[j];
            cb[j] = (unsigned)(p >> 32);
            ci[j] = (unsigned short)p;
        }
        if (tid == 0) { cur_s = 0u; k_s = K_TOP; }
        __syncthreads();

        // ---- 4x8-bit radix select: exact K-th largest ----
        #pragma unroll
        for (int pass = 0; pass < 4; ++pass) {
            const int shift = 24 - 8 * pass;
            hist[tid] = 0;                       // NT2 == 256
            __syncthreads();

            const unsigned cur = cur_s;
            const int k = k_s;
            for (int j = tid; j < ncand; j += NT2) {
                unsigned u = cb[j];
                bool match = (pass == 0) || ((u >> (shift + 8)) == cur);
                if (match) atomicAdd(&hist[(u >> shift) & 255u], 1);
            }
            __syncthreads();

            if (tid < 32) {
                int h[8]; int s = 0;
                #pragma unroll
                for (int q = 0; q < 8; ++q) { h[q] = hist[255 - 8 * lane - q]; s += h[q]; }
                int pre = s;
                #pragma unroll
                for (int d = 1; d < 32; d <<= 1) {
                    int t2 = __shfl_up_sync(0xffffffffu, pre, d);
                    if (lane >= d) pre += t2;
                }
                pre -= s;   // count of strictly larger digits
                bool hit = (pre < k) && (pre + s >= k);
                unsigned hm = __ballot_sync(0xffffffffu, hit);
                int hl = __ffs(hm) - 1;
                if (lane == hl) {
                    int acc = pre;
                    #pragma unroll
                    for (int q = 0; q < 8; ++q) {
                        int d = 255 - 8 * lane - q;
                        if (acc + h[q] >= k) { cur_s = (cur << 8) | (unsigned)d; k_s = k - acc; break; }
                        acc += h[q];
                    }
                }
            }
            __syncthreads();
        }
        const unsigned thr_bits = cur_s;     // K-th largest (positive float bits)
        const int      need_eq  = k_s;       // # tied-at-threshold to keep
        const float    thr_f    = __uint_as_float(thr_bits);

        // ---- scatter strictly-greater; collect boundary ties ----
        for (int j = tid; j < ncand; j += NT2) {
            unsigned u = cb[j];
            if (u > thr_bits) {
                orow[ci[j]] = fmaxf(__uint_as_float(u), 0.f);
            } else if (u == thr_bits) {
                int p = atomicAdd(&eq_cnt, 1);
                if (p < EQCAP) eq_idx[p] = ci[j];
            }
        }
        __syncthreads();

        // XLA tie-break: among equal values, lowest indices win
        const int ce = (eq_cnt < EQCAP) ? eq_cnt : EQCAP;
        const float thr_relu = fmaxf(thr_f, 0.f);
        for (int j = tid; j < ce; j += NT2) {
            const unsigned short me = eq_idx[j];
            int r = 0;
            for (int i = 0; i < ce; ++i) r += (eq_idx[i] < me) ? 1 : 0;
            if (r < need_eq) orow[me] = thr_relu;
        }
    } else {
        // ---- slow path: exact, reads raw row (never triggers on N(0,1) input) ----
        // output row already zeroed by kernel 1
        unsigned thr = 0u;
        for (int b = 31; b >= 0; --b) {
            const unsigned T = thr | (1u << b);
            if (tid == 0) cnt_s = 0;
            __syncthreads();
            int c = 0;
            for (int j = tid; j < COLS; j += NT2)
                c += (sortable_bits(xrow[j]) >= T) ? 1 : 0;
            #pragma unroll
            for (int d = 16; d; d >>= 1) c += __shfl_down_sync(0xffffffffu, c, d);
            if (lane == 0) atomicAdd(&cnt_s, c);
            __syncthreads();
            if (cnt_s >= K_TOP) thr = T;
            __syncthreads();
        }

        if (tid == 0) cnt_s = 0;
        __syncthreads();
        {
            int c = 0;
            for (int j = tid; j < COLS; j += NT2)
                c += (sortable_bits(xrow[j]) > thr) ? 1 : 0;
            #pragma unroll
            for (int d = 16; d; d >>= 1) c += __shfl_down_sync(0xffffffffu, c, d);
            if (lane == 0) atomicAdd(&cnt_s, c);
        }
        __syncthreads();
        const int need_eq = K_TOP - cnt_s;
        __syncthreads();

        for (int j = tid; j < COLS; j += NT2) {
            float v = xrow[j];
            unsigned s = sortable_bits(v);
            if (s > thr) {
                orow[j] = fmaxf(v, 0.f);
            } else if (s == thr) {
                int p = atomicAdd(&eq_cnt, 1);
                if (p < EQCAP) eq_idx[p] = (unsigned short)j;
            }
        }
        __syncthreads();
        const int ce = (eq_cnt < EQCAP) ? eq_cnt : EQCAP;
        const float thr_relu = fmaxf(unsortable_bits(thr), 0.f);
        for (int j = tid; j < ce; j += NT2) {
            const unsigned short me = eq_idx[j];
            int r = 0;
            for (int i = 0; i < ce; ++i) r += (eq_idx[i] < me) ? 1 : 0;
            if (r < need_eq) orow[me] = thr_relu;
        }
    }
}

extern "C" void kernel_launch(void* const* d_in, const int* in_sizes, int n_in,
                              void* d_out, int out_size) {
    const float* x = (const float*)d_in[0];
    float* out = (float*)d_out;
    const int rows = in_sizes[0] / COLS;
    stream_compact_kernel<<<rows, NT1>>>(x, out);
    select_scatter_kernel<<<rows, NT2>>>(x, out);
}